// round 11
// baseline (speedup 1.0000x reference)
#include <cuda_runtime.h>
#include <cuda_fp16.h>
#include <cstdint>

constexpr int ND = 30000, D = 256, R = 8, KW = 2048;
constexpr int NCH    = 36;                    // K chunks of 64 (2304/64)
constexpr int MTILE  = 64;
constexpr int GRID_M = (ND + MTILE - 1) / MTILE;   // 469
constexpr int THREADS = 512;

// smem layout (bytes)
constexpr int SINV_OFF  = 0;                  // 512 floats = 2048
constexpr int A32_OFF   = 2048;
constexpr int A32_STAGE = 64 * 272;           // 17408 (64 rows x 64 f32, 272B stride)
constexpr int A16_OFF   = A32_OFF + 3 * A32_STAGE;   // 54272
constexpr int A16_STAGE = 64 * 144;           // 9216
constexpr int B_OFF     = A16_OFF + 2 * A16_STAGE;   // 72704
constexpr int B_STAGE   = 512 * 144;          // 73728
constexpr int H_OFF     = A32_OFF;            // alias: A32 dead after main loop
constexpr int H_STRIDE  = 528;
constexpr int SMEM_T    = B_OFF + 2 * B_STAGE;       // 220160

// device scratch (no allocations allowed)
__device__ float  g_sum[(size_t)ND * KW];           // f32 per-(dst,rel) sums (proven)
__device__ float  g_cnt[ND * R];
__device__ __half g_Bh[(size_t)2 * NCH * 256 * 64]; // [L][kc][n][k64] fp16
__device__ __half g_r2h[256 * 256];                 // root2 transposed [n][k]

// ---------------------------------------------------------------------------
__device__ __forceinline__ void mma_f16(float* c, const uint32_t* a,
                                        uint32_t b0, uint32_t b1) {
    asm volatile(
        "mma.sync.aligned.m16n8k16.row.col.f32.f16.f16.f32 "
        "{%0,%1,%2,%3}, {%4,%5,%6,%7}, {%8,%9}, {%0,%1,%2,%3};"
        : "+f"(c[0]), "+f"(c[1]), "+f"(c[2]), "+f"(c[3])
        : "r"(a[0]), "r"(a[1]), "r"(a[2]), "r"(a[3]), "r"(b0), "r"(b1));
}
__device__ __forceinline__ void ldsm_x4(uint32_t* r, uint32_t addr) {
    asm volatile("ldmatrix.sync.aligned.m8n8.x4.shared.b16 {%0,%1,%2,%3}, [%4];"
                 : "=r"(r[0]), "=r"(r[1]), "=r"(r[2]), "=r"(r[3]) : "r"(addr));
}
__device__ __forceinline__ void cp_async16(void* smem_dst, const void* gsrc) {
    uint32_t s = (uint32_t)__cvta_generic_to_shared(smem_dst);
    asm volatile("cp.async.cg.shared.global [%0], [%1], 16;" :: "r"(s), "l"(gsrc));
}
#define CP_COMMIT() asm volatile("cp.async.commit_group;" ::: "memory")
#define CP_WAIT(n)  asm volatile("cp.async.wait_group %0;" :: "n"(n) : "memory")

// ---------------------------------------------------------------------------
// Kernel 0: prep — fp16 weights [L][kc64][n][k64]; root2 transposed [n][k]
// ---------------------------------------------------------------------------
__global__ void prep_kernel(const float* __restrict__ w1, const float* __restrict__ r1,
                            const float* __restrict__ w2, const float* __restrict__ r2) {
    int gid = blockIdx.x * blockDim.x + threadIdx.x;
    if (gid < 2 * NCH * 256 * 8) {
        int L   = gid / (NCH * 256 * 8);
        int rem = gid % (NCH * 256 * 8);
        int kc  = rem >> 11;
        int n   = (rem >> 3) & 255;
        int c8  = rem & 7;
        __half h8[8];
#pragma unroll
        for (int j = 0; j < 8; j++) {
            int k = kc * 64 + c8 * 8 + j;
            float x;
            if (L == 0) x = (k < KW) ? w1[(size_t)k * D + n] : r1[(size_t)(k - KW) * D + n];
            else        x = (k < KW) ? w2[(size_t)k * D + n] : 0.f;
            h8[j] = __float2half_rn(x);
        }
        *(uint4*)(g_Bh + ((size_t)(L * NCH + kc) * 256 + n) * 64 + c8 * 8) = *(uint4*)h8;
    }
    if (gid < 256 * 32) {
        int n = gid >> 5, c8 = gid & 31;
        __half h8[8];
#pragma unroll
        for (int j = 0; j < 8; j++)
            h8[j] = __float2half_rn(r2[(size_t)(c8 * 8 + j) * 256 + n]);
        *(uint4*)(g_r2h + (size_t)n * 256 + c8 * 8) = *(uint4*)h8;
    }
}

// ---------------------------------------------------------------------------
// Kernel 1: zero f32 sums + counts
// ---------------------------------------------------------------------------
__global__ void zero_kernel() {
    size_t stride = (size_t)gridDim.x * blockDim.x;
    size_t i = (size_t)blockIdx.x * blockDim.x + threadIdx.x;
    float4 z = make_float4(0.f, 0.f, 0.f, 0.f);
    size_t nsum4 = (size_t)ND * KW / 4;
    for (size_t j = i; j < nsum4; j += stride) ((float4*)g_sum)[j] = z;
    size_t ncnt4 = (size_t)ND * R / 4;
    for (size_t j = i; j < ncnt4; j += stride) ((float4*)g_cnt)[j] = z;
}

// ---------------------------------------------------------------------------
// Kernel 2: f32 scatter-add (one warp per edge)
// ---------------------------------------------------------------------------
__global__ void scatter_kernel(const float* __restrict__ x_src,
                               const void*  __restrict__ ei,
                               const void*  __restrict__ et, int E) {
    int gw   = (blockIdx.x * blockDim.x + threadIdx.x) >> 5;
    int lane = threadIdx.x & 31;
    if (gw >= E) return;

    const int* ei32 = (const int*)ei;
    bool is64 = ((ei32[1] | ei32[3] | ei32[5] | ei32[7]) == 0);

    long long s, d, r;
    if (is64) {
        const long long* p = (const long long*)ei;
        s = p[gw]; d = p[E + gw]; r = ((const long long*)et)[gw];
    } else {
        s = ei32[gw]; d = ei32[E + gw]; r = ((const int*)et)[gw];
    }

    const float4* xr  = (const float4*)(x_src + (size_t)s * D);
    float4*       dst = (float4*)(g_sum + ((size_t)d * R + r) * D);
#pragma unroll
    for (int it = 0; it < 2; it++) {
        float4 v = __ldg(xr + lane + 32 * it);
        asm volatile("red.global.add.v4.f32 [%0], {%1,%2,%3,%4};"
                     :: "l"(dst + lane + 32 * it),
                        "f"(v.x), "f"(v.y), "f"(v.z), "f"(v.w) : "memory");
    }
    if (lane == 0) atomicAdd(&g_cnt[d * R + r], 1.0f);
}

// ---------------------------------------------------------------------------
// Kernel 3: fully-fused fp16 GEMM, 512 threads, BK=64, ldmatrix fragments.
//   A path: cp.async f32 (3-stage, 2-chunk lookahead) -> in-smem scale+cvt.
//   warps 0-7: layer1 -> h (relu) in smem; warps 8-15: layer2 (+ h@root2)
// ---------------------------------------------------------------------------
__global__ __launch_bounds__(THREADS, 1)
void fused_all(const float* __restrict__ x_dst,
               const float* __restrict__ b1,
               const float* __restrict__ b2,
               float* __restrict__ out) {
    extern __shared__ char smx[];
    float* s_inv = (float*)(smx + SINV_OFF);
    uint32_t smb = (uint32_t)__cvta_generic_to_shared(smx);

    int tid = threadIdx.x, wid = tid >> 5, lane = tid & 31;
    int g = lane >> 2, t = lane & 3;
    int L = wid >> 3, sub = wid & 7;
    int wm = (sub >> 2) * 32;       // 0 / 32
    int cb = (sub & 3) * 64;        // 0 / 64 / 128 / 192
    int row0 = blockIdx.x * MTILE;

    // ldmatrix per-lane offsets, strides 144 / 528
    int lr = lane & 7, lh = (lane >> 3) & 1, lc = (lane >> 4) & 1;
    uint32_t a_loff  = (uint32_t)((wm + lr + lh * 8) * 144 + lc * 16);
    uint32_t b_loff  = (uint32_t)((L * 256 + cb + lr + lc * 8) * 144 + lh * 16);
    uint32_t br_loff = (uint32_t)((cb + lr + lc * 8) * 144 + lh * 16);
    uint32_t h_loff  = (uint32_t)((wm + lr + lh * 8) * H_STRIDE + lc * 16);

    {
        int rl = tid >> 3, rr = tid & 7, grow = row0 + rl;  // 512 == MTILE*R
        float c = (grow < ND) ? g_cnt[grow * R + rr] : 1.0f;
        s_inv[tid] = 1.0f / fmaxf(c, 1.0f);
    }
    __syncthreads();

    float acc[2][8][4];
#pragma unroll
    for (int mi = 0; mi < 2; mi++)
#pragma unroll
        for (int nj = 0; nj < 8; nj++)
#pragma unroll
            for (int q = 0; q < 4; q++) acc[mi][nj][q] = 0.f;

    auto ldA32 = [&](int kc, int s) {
#pragma unroll
        for (int i = 0; i < 2; i++) {
            int idx = tid + i * 512;            // 1024 x 16B = 64 rows x 256B
            int row = idx & 63, c = idx >> 6;   // c 0..15
            int grow = row0 + row;
            if (grow >= ND) grow = 0;           // clamp: finite junk, never stored
            const float* src = (kc < 32)
                ? g_sum + (size_t)grow * KW + kc * 64 + c * 4
                : x_dst + (size_t)grow * D + (kc - 32) * 64 + c * 4;
            cp_async16(smx + A32_OFF + s * A32_STAGE + row * 272 + c * 16, src);
        }
    };
    auto cvtA = [&](int kc, int s32, int s16) {
        int rl = tid & 63, c8 = tid >> 6;       // row, 8-float group
        const char* p = smx + A32_OFF + s32 * A32_STAGE + rl * 272 + c8 * 32;
        float4 v0 = *(const float4*)p;
        float4 v1 = *(const float4*)(p + 16);
        float sc = (kc < 32) ? s_inv[rl * 8 + (kc >> 2)] : 1.0f;
        __half h8[8];
        h8[0] = __float2half_rn(v0.x * sc);
        h8[1] = __float2half_rn(v0.y * sc);
        h8[2] = __float2half_rn(v0.z * sc);
        h8[3] = __float2half_rn(v0.w * sc);
        h8[4] = __float2half_rn(v1.x * sc);
        h8[5] = __float2half_rn(v1.y * sc);
        h8[6] = __float2half_rn(v1.z * sc);
        h8[7] = __float2half_rn(v1.w * sc);
        *(uint4*)(smx + A16_OFF + s16 * A16_STAGE + rl * 144 + c8 * 16) = *(uint4*)h8;
    };
    auto ldB = [&](int kc, int s) {
#pragma unroll
        for (int i = 0; i < 8; i++) {
            int idx = tid + i * 512;            // 4096 x 16B
            int n5 = idx >> 3, c8 = idx & 7;
            int Lx = n5 >> 8, n = n5 & 255;
            cp_async16(smx + B_OFF + s * B_STAGE + n5 * 144 + c8 * 16,
                       g_Bh + ((size_t)(Lx * NCH + kc) * 256 + n) * 64 + c8 * 8);
        }
    };
    auto ldRootB = [&](int c, int s) {
#pragma unroll
        for (int i = 0; i < 4; i++) {
            int idx = tid + i * 512;            // 2048 x 16B
            int n = idx >> 3, c8 = idx & 7;
            cp_async16(smx + B_OFF + s * B_STAGE + n * 144 + c8 * 16,
                       g_r2h + (size_t)n * 256 + c * 64 + c8 * 8);
        }
    };
    auto compute = [&](int s16, int sB) {
        uint32_t Ab = smb + A16_OFF + s16 * A16_STAGE + a_loff;
        uint32_t Bb = smb + B_OFF + sB * B_STAGE + b_loff;
#pragma unroll
        for (int ks = 0; ks < 4; ks++) {
            uint32_t a0[4], a1[4];
            ldsm_x4(a0, Ab + ks * 32);
            ldsm_x4(a1, Ab + 16 * 144 + ks * 32);
#pragma unroll
            for (int p = 0; p < 4; p++) {
                uint32_t b[4];
                ldsm_x4(b, Bb + p * 16 * 144 + ks * 32);
                mma_f16(acc[0][2 * p],     a0, b[0], b[1]);
                mma_f16(acc[0][2 * p + 1], a0, b[2], b[3]);
                mma_f16(acc[1][2 * p],     a1, b[0], b[1]);
                mma_f16(acc[1][2 * p + 1], a1, b[2], b[3]);
            }
        }
    };

    // ---- prologue ----
    // Group order is load-bearing for the split waits below.
    ldA32(0, 0); CP_COMMIT();        // G1
    ldB(0, 0);  CP_COMMIT();         // G2 = GB[-1]
    ldA32(1, 1); CP_COMMIT();        // G3 = GA[-1]
    CP_WAIT(2);                      // G1 done -> A32(0) ready
    __syncthreads();
    cvtA(0, 0, 0);                   // A16 stage 0 (visible at iter-0 barrier)

    // ---- main loop: per iter, wait(1) -> B(k) ready (A32(k+1) still flying);
    // after compute, wait(2) -> A32(k+1) ready (B(k+1), A32(k+2) still flying).
    // All smem writes occur after the per-iter barrier; every reused stage's
    // previous reader finished >=1 barrier earlier (S_B=2, S_A32=3, S_A16=2).
    for (int k = 0; k < NCH; k++) {
        CP_WAIT(1);
        __syncthreads();
        if (k + 1 < NCH) ldB(k + 1, (k + 1) & 1);
        CP_COMMIT();                             // GB[k] (may be empty)
        if (k + 2 < NCH) ldA32(k + 2, (k + 2) % 3);
        CP_COMMIT();                             // GA[k] (may be empty)
        compute(k & 1, k & 1);
        CP_WAIT(2);                              // GA[k-1] done -> A32(k+1)
        if (k + 1 < NCH) cvtA(k + 1, (k + 1) % 3, (k + 1) & 1);
    }
    __syncthreads();

    // ---- root2 prologue + layer1 epilogue (h -> smem fp16, aliases A32) ----
    ldRootB(0, 0); CP_COMMIT();
    if (L == 0) {
#pragma unroll
        for (int mi = 0; mi < 2; mi++) {
#pragma unroll
            for (int nj = 0; nj < 8; nj++) {
                int col = cb + nj * 8 + 2 * t;
                float ba = __ldg(&b1[col]), bb = __ldg(&b1[col + 1]);
                __half2 h0 = __floats2half2_rn(fmaxf(acc[mi][nj][0] + ba, 0.f),
                                               fmaxf(acc[mi][nj][1] + bb, 0.f));
                __half2 h1 = __floats2half2_rn(fmaxf(acc[mi][nj][2] + ba, 0.f),
                                               fmaxf(acc[mi][nj][3] + bb, 0.f));
                int r = wm + mi * 16 + g;
                *(__half2*)(smx + H_OFF + r * H_STRIDE + col * 2)       = h0;
                *(__half2*)(smx + H_OFF + (r + 8) * H_STRIDE + col * 2) = h1;
            }
        }
    }
    __syncthreads();

    // ---- root phase: layer2 acc += h @ root2 (4 chunks of K=64) ----
    for (int c = 0; c < 4; c++) {
        int s = c & 1;
        CP_WAIT(0);
        __syncthreads();
        if (c + 1 < 4) { ldRootB(c + 1, s ^ 1); CP_COMMIT(); }
        if (L == 1) {
            uint32_t Hb = smb + H_OFF + h_loff + c * 128;
            uint32_t Bb = smb + B_OFF + s * B_STAGE + br_loff;
#pragma unroll
            for (int ks = 0; ks < 4; ks++) {
                uint32_t a0[4], a1[4];
                ldsm_x4(a0, Hb + ks * 32);
                ldsm_x4(a1, Hb + 16 * H_STRIDE + ks * 32);
#pragma unroll
                for (int p = 0; p < 4; p++) {
                    uint32_t b[4];
                    ldsm_x4(b, Bb + p * 16 * 144 + ks * 32);
                    mma_f16(acc[0][2 * p],     a0, b[0], b[1]);
                    mma_f16(acc[0][2 * p + 1], a0, b[2], b[3]);
                    mma_f16(acc[1][2 * p],     a1, b[0], b[1]);
                    mma_f16(acc[1][2 * p + 1], a1, b[2], b[3]);
                }
            }
        }
        __syncthreads();
    }

    // ---- layer2 final store ----
    if (L == 1) {
#pragma unroll
        for (int mi = 0; mi < 2; mi++) {
            int r0g = row0 + wm + mi * 16 + g;
#pragma unroll
            for (int nj = 0; nj < 8; nj++) {
                int col = cb + nj * 8 + 2 * t;
                float ba = __ldg(&b2[col]), bb = __ldg(&b2[col + 1]);
                if (r0g < ND)
                    *(float2*)(out + (size_t)r0g * D + col) =
                        make_float2(acc[mi][nj][0] + ba, acc[mi][nj][1] + bb);
                if (r0g + 8 < ND)
                    *(float2*)(out + (size_t)(r0g + 8) * D + col) =
                        make_float2(acc[mi][nj][2] + ba, acc[mi][nj][3] + bb);
            }
        }
    }
}

// ---------------------------------------------------------------------------
extern "C" void kernel_launch(void* const* d_in, const int* in_sizes, int n_in,
                              void* d_out, int out_size) {
    const float* x_src = (const float*)d_in[0];
    const float* x_dst = (const float*)d_in[1];
    const void*  ei    = d_in[2];
    const void*  et    = d_in[3];
    const float* w1    = (const float*)d_in[4];
    const float* root1 = (const float*)d_in[5];
    const float* b1    = (const float*)d_in[6];
    const float* w2    = (const float*)d_in[7];
    const float* root2 = (const float*)d_in[8];
    const float* b2    = (const float*)d_in[9];
    float* out = (float*)d_out;
    int E = in_sizes[3];

    cudaFuncSetAttribute(fused_all, cudaFuncAttributeMaxDynamicSharedMemorySize, SMEM_T);

    prep_kernel<<<(2 * NCH * 256 * 8 + 255) / 256, 256>>>(w1, root1, w2, root2);
    zero_kernel<<<2368, 256>>>();
    scatter_kernel<<<(E + 7) / 8, 256>>>(x_src, ei, et, E);

    fused_all<<<GRID_M, THREADS, SMEM_T>>>(x_dst, b1, b2, out);
}

// round 12
// speedup vs baseline: 1.3105x; 1.3105x over previous
#include <cuda_runtime.h>
#include <cuda_fp16.h>
#include <cstdint>

constexpr int ND = 30000, D = 256, R = 8, KW = 2048;
constexpr int NCH    = 36;                    // K chunks of 64 (2304/64)
constexpr int MTILE  = 64;
constexpr int GRID_M = (ND + MTILE - 1) / MTILE;   // 469
constexpr int THREADS = 512;

// smem layout (bytes). Row strides 144 / 528 are ≡16 (mod 128): conflict-free ldmatrix.
constexpr int SINV_OFF = 0;                   // 512 floats
constexpr int A_OFF    = 2048;
constexpr int A_STAGE  = 64 * 144;            // 9216
constexpr int B_OFF    = A_OFF + 2 * A_STAGE; // 20480
constexpr int B_STAGE  = 512 * 144;           // 73728
constexpr int H_OFF    = B_OFF + 2 * B_STAGE; // 167936
constexpr int H_STRIDE = 528;
constexpr int SMEM_T   = H_OFF + 64 * H_STRIDE;   // 201728

// device scratch (no allocations allowed)
__device__ __half g_sumh[(size_t)ND * KW];          // fp16 per-(dst,rel) sums
__device__ float  g_cnt[ND * R];
__device__ __half g_xsh[(size_t)ND * D];            // x_src fp16
__device__ __half g_xdh[(size_t)ND * D];            // x_dst fp16
__device__ __half g_Bh[(size_t)2 * NCH * 256 * 64]; // [L][kc][n][k64] fp16
__device__ __half g_r2h[256 * 256];                 // root2 transposed [n][k]

// ---------------------------------------------------------------------------
__device__ __forceinline__ void mma_f16(float* c, const uint32_t* a,
                                        uint32_t b0, uint32_t b1) {
    asm volatile(
        "mma.sync.aligned.m16n8k16.row.col.f32.f16.f16.f32 "
        "{%0,%1,%2,%3}, {%4,%5,%6,%7}, {%8,%9}, {%0,%1,%2,%3};"
        : "+f"(c[0]), "+f"(c[1]), "+f"(c[2]), "+f"(c[3])
        : "r"(a[0]), "r"(a[1]), "r"(a[2]), "r"(a[3]), "r"(b0), "r"(b1));
}
__device__ __forceinline__ void ldsm_x4(uint32_t* r, uint32_t addr) {
    asm volatile("ldmatrix.sync.aligned.m8n8.x4.shared.b16 {%0,%1,%2,%3}, [%4];"
                 : "=r"(r[0]), "=r"(r[1]), "=r"(r[2]), "=r"(r[3]) : "r"(addr));
}
__device__ __forceinline__ void cp_async16(void* smem_dst, const void* gsrc) {
    uint32_t s = (uint32_t)__cvta_generic_to_shared(smem_dst);
    asm volatile("cp.async.cg.shared.global [%0], [%1], 16;" :: "r"(s), "l"(gsrc));
}
#define CP_COMMIT() asm volatile("cp.async.commit_group;" ::: "memory")
#define CP_WAIT0()  asm volatile("cp.async.wait_group 0;" ::: "memory")

// ---------------------------------------------------------------------------
// Kernel 0: prep — fp16 weights [L][kc64][n][k64]; root2 [n][k]; x_src/x_dst fp16
// ---------------------------------------------------------------------------
__global__ void prep_kernel(const float* __restrict__ w1, const float* __restrict__ r1,
                            const float* __restrict__ w2, const float* __restrict__ r2,
                            const float* __restrict__ xs, const float* __restrict__ xd) {
    int gid = blockIdx.x * blockDim.x + threadIdx.x;
    if (gid < 2 * NCH * 256 * 8) {
        int L   = gid / (NCH * 256 * 8);
        int rem = gid % (NCH * 256 * 8);
        int kc  = rem >> 11;
        int n   = (rem >> 3) & 255;
        int c8  = rem & 7;
        __half h8[8];
#pragma unroll
        for (int j = 0; j < 8; j++) {
            int k = kc * 64 + c8 * 8 + j;
            float x;
            if (L == 0) x = (k < KW) ? w1[(size_t)k * D + n] : r1[(size_t)(k - KW) * D + n];
            else        x = (k < KW) ? w2[(size_t)k * D + n] : 0.f;
            h8[j] = __float2half_rn(x);
        }
        *(uint4*)(g_Bh + ((size_t)(L * NCH + kc) * 256 + n) * 64 + c8 * 8) = *(uint4*)h8;
    }
    if (gid < 256 * 32) {
        int n = gid >> 5, c8 = gid & 31;
        __half h8[8];
#pragma unroll
        for (int j = 0; j < 8; j++)
            h8[j] = __float2half_rn(r2[(size_t)(c8 * 8 + j) * 256 + n]);
        *(uint4*)(g_r2h + (size_t)n * 256 + c8 * 8) = *(uint4*)h8;
    }
    if (gid < ND * D / 4) {
        float4 vs = __ldg((const float4*)xs + gid);
        float4 vd = __ldg((const float4*)xd + gid);
        ((__half2*)g_xsh)[gid * 2]     = __floats2half2_rn(vs.x, vs.y);
        ((__half2*)g_xsh)[gid * 2 + 1] = __floats2half2_rn(vs.z, vs.w);
        ((__half2*)g_xdh)[gid * 2]     = __floats2half2_rn(vd.x, vd.y);
        ((__half2*)g_xdh)[gid * 2 + 1] = __floats2half2_rn(vd.z, vd.w);
    }
}

// ---------------------------------------------------------------------------
// Kernel 1: zero fp16 sums + counts
// ---------------------------------------------------------------------------
__global__ void zero_kernel() {
    size_t stride = (size_t)gridDim.x * blockDim.x;
    size_t i = (size_t)blockIdx.x * blockDim.x + threadIdx.x;
    uint4 z = make_uint4(0, 0, 0, 0);
    size_t n16 = (size_t)ND * KW / 8;         // uint4 = 8 halfs
    for (size_t j = i; j < n16; j += stride) ((uint4*)g_sumh)[j] = z;
    size_t nc4 = (size_t)ND * R / 4;
    for (size_t j = i; j < nc4; j += stride)
        ((float4*)g_cnt)[j] = make_float4(0.f, 0.f, 0.f, 0.f);
}

// ---------------------------------------------------------------------------
// Kernel 2: fp16 scatter-add (one warp per edge), one red.v4.f16x2 per lane
// ---------------------------------------------------------------------------
__global__ void scatter_kernel(const void* __restrict__ ei,
                               const void* __restrict__ et, int E) {
    int gw   = (blockIdx.x * blockDim.x + threadIdx.x) >> 5;
    int lane = threadIdx.x & 31;
    if (gw >= E) return;

    const int* ei32 = (const int*)ei;
    bool is64 = ((ei32[1] | ei32[3] | ei32[5] | ei32[7]) == 0);

    long long s, d, r;
    if (is64) {
        const long long* p = (const long long*)ei;
        s = p[gw]; d = p[E + gw]; r = ((const long long*)et)[gw];
    } else {
        s = ei32[gw]; d = ei32[E + gw]; r = ((const int*)et)[gw];
    }

    uint4 v = __ldg((const uint4*)(g_xsh + (size_t)s * D) + lane);
    uint4* dst = (uint4*)(g_sumh + ((size_t)d * R + r) * D) + lane;
    asm volatile("red.global.add.noftz.v4.f16x2 [%0], {%1,%2,%3,%4};"
                 :: "l"(dst), "r"(v.x), "r"(v.y), "r"(v.z), "r"(v.w) : "memory");
    if (lane == 0) atomicAdd(&g_cnt[d * R + r], 1.0f);
}

// ---------------------------------------------------------------------------
// Kernel 3: fully-fused fp16 GEMM — EXACT round-10 structure; only the A
// source changed (fp16 g_sumh / g_xdh instead of f32), scale still in f32.
// ---------------------------------------------------------------------------
__global__ __launch_bounds__(THREADS, 1)
void fused_all(const float* __restrict__ b1,
               const float* __restrict__ b2,
               float* __restrict__ out) {
    extern __shared__ char smx[];
    float* s_inv = (float*)(smx + SINV_OFF);
    uint32_t smb = (uint32_t)__cvta_generic_to_shared(smx);

    int tid = threadIdx.x, wid = tid >> 5, lane = tid & 31;
    int g = lane >> 2, t = lane & 3;
    int L = wid >> 3, sub = wid & 7;
    int wm = (sub >> 2) * 32;       // 0 / 32
    int cb = (sub & 3) * 64;        // 0 / 64 / 128 / 192
    int row0 = blockIdx.x * MTILE;

    int lr = lane & 7, lh = (lane >> 3) & 1, lc = (lane >> 4) & 1;
    uint32_t a_loff  = (uint32_t)((wm + lr + lh * 8) * 144 + lc * 16);
    uint32_t b_loff  = (uint32_t)((L * 256 + cb + lr + lc * 8) * 144 + lh * 16);
    uint32_t br_loff = (uint32_t)((cb + lr + lc * 8) * 144 + lh * 16);
    uint32_t h_loff  = (uint32_t)((wm + lr + lh * 8) * H_STRIDE + lc * 16);

    {
        int rl = tid >> 3, rr = tid & 7, grow = row0 + rl;  // 512 == MTILE*R
        float c = (grow < ND) ? g_cnt[grow * R + rr] : 1.0f;
        s_inv[tid] = 1.0f / fmaxf(c, 1.0f);
    }
    __syncthreads();

    float acc[2][8][4];
#pragma unroll
    for (int mi = 0; mi < 2; mi++)
#pragma unroll
        for (int nj = 0; nj < 8; nj++)
#pragma unroll
            for (int q = 0; q < 4; q++) acc[mi][nj][q] = 0.f;

    uint4 av; float asc; bool ascale;
    auto ldA = [&](int kc) {
        int rl = tid >> 3, c8 = tid & 7;        // row, 8-half group
        int grow = row0 + rl;
        av = make_uint4(0, 0, 0, 0);
        ascale = false; asc = 1.0f;
        if (grow < ND) {
            if (kc < 32) {
                av = __ldg((const uint4*)(g_sumh + (size_t)grow * KW + kc * 64) + c8);
                asc = s_inv[rl * R + (kc >> 2)];
                ascale = true;
            } else {
                av = __ldg((const uint4*)(g_xdh + (size_t)grow * D + (kc - 32) * 64) + c8);
            }
        }
    };
    auto stA = [&](int s) {
        int rl = tid >> 3, c8 = tid & 7;
        uint4 w = av;
        if (ascale) {
            const __half* hv = (const __half*)&av;
            __half h8[8];
#pragma unroll
            for (int j = 0; j < 8; j++)
                h8[j] = __float2half_rn(__half2float(hv[j]) * asc);
            w = *(uint4*)h8;
        }
        *(uint4*)(smx + A_OFF + s * A_STAGE + rl * 144 + c8 * 16) = w;
    };
    auto ldB = [&](int kc, int s) {
#pragma unroll
        for (int i = 0; i < 8; i++) {
            int idx = tid + i * 512;            // 4096 x 16B
            int n5 = idx >> 3, c8 = idx & 7;
            int Lx = n5 >> 8, n = n5 & 255;
            cp_async16(smx + B_OFF + s * B_STAGE + n5 * 144 + c8 * 16,
                       g_Bh + ((size_t)(Lx * NCH + kc) * 256 + n) * 64 + c8 * 8);
        }
    };
    auto ldRootB = [&](int c, int s) {
#pragma unroll
        for (int i = 0; i < 4; i++) {
            int idx = tid + i * 512;            // 2048 x 16B
            int n = idx >> 3, c8 = idx & 7;
            cp_async16(smx + B_OFF + s * B_STAGE + n * 144 + c8 * 16,
                       g_r2h + (size_t)n * 256 + c * 64 + c8 * 8);
        }
    };
    auto compute = [&](int s) {
        uint32_t Ab = smb + A_OFF + s * A_STAGE + a_loff;
        uint32_t Bb = smb + B_OFF + s * B_STAGE + b_loff;
#pragma unroll
        for (int ks = 0; ks < 4; ks++) {
            uint32_t a0[4], a1[4];
            ldsm_x4(a0, Ab + ks * 32);
            ldsm_x4(a1, Ab + 16 * 144 + ks * 32);
#pragma unroll
            for (int p = 0; p < 4; p++) {
                uint32_t b[4];
                ldsm_x4(b, Bb + p * 16 * 144 + ks * 32);
                mma_f16(acc[0][2 * p],     a0, b[0], b[1]);
                mma_f16(acc[0][2 * p + 1], a0, b[2], b[3]);
                mma_f16(acc[1][2 * p],     a1, b[0], b[1]);
                mma_f16(acc[1][2 * p + 1], a1, b[2], b[3]);
            }
        }
    };

    // ---- main loop: 36 chunks of K=64; S=2, round-10-proven structure ----
    ldB(0, 0); CP_COMMIT();
    ldA(0); stA(0);
    CP_WAIT0();
    __syncthreads();

    for (int k = 0; k < NCH; k++) {
        int s = k & 1;
        if (k + 1 < NCH) { ldB(k + 1, s ^ 1); CP_COMMIT(); ldA(k + 1); }
        compute(s);
        if (k + 1 < NCH) { CP_WAIT0(); stA(s ^ 1); }
        __syncthreads();
    }

    // ---- root2 prologue + layer1 epilogue (h -> smem fp16) ----
    ldRootB(0, 0); CP_COMMIT();
    if (L == 0) {
#pragma unroll
        for (int mi = 0; mi < 2; mi++) {
#pragma unroll
            for (int nj = 0; nj < 8; nj++) {
                int col = cb + nj * 8 + 2 * t;
                float ba = __ldg(&b1[col]), bb = __ldg(&b1[col + 1]);
                __half2 h0 = __floats2half2_rn(fmaxf(acc[mi][nj][0] + ba, 0.f),
                                               fmaxf(acc[mi][nj][1] + bb, 0.f));
                __half2 h1 = __floats2half2_rn(fmaxf(acc[mi][nj][2] + ba, 0.f),
                                               fmaxf(acc[mi][nj][3] + bb, 0.f));
                int r = wm + mi * 16 + g;
                *(__half2*)(smx + H_OFF + r * H_STRIDE + col * 2)       = h0;
                *(__half2*)(smx + H_OFF + (r + 8) * H_STRIDE + col * 2) = h1;
            }
        }
    }
    __syncthreads();

    // ---- root phase: layer2 acc += h @ root2 (4 chunks of K=64) ----
    for (int c = 0; c < 4; c++) {
        int s = c & 1;
        CP_WAIT0();
        __syncthreads();
        if (c + 1 < 4) { ldRootB(c + 1, s ^ 1); CP_COMMIT(); }
        if (L == 1) {
            uint32_t Hb = smb + H_OFF + h_loff + c * 128;
            uint32_t Bb = smb + B_OFF + s * B_STAGE + br_loff;
#pragma unroll
            for (int ks = 0; ks < 4; ks++) {
                uint32_t a0[4], a1[4];
                ldsm_x4(a0, Hb + ks * 32);
                ldsm_x4(a1, Hb + 16 * H_STRIDE + ks * 32);
#pragma unroll
                for (int p = 0; p < 4; p++) {
                    uint32_t b[4];
                    ldsm_x4(b, Bb + p * 16 * 144 + ks * 32);
                    mma_f16(acc[0][2 * p],     a0, b[0], b[1]);
                    mma_f16(acc[0][2 * p + 1], a0, b[2], b[3]);
                    mma_f16(acc[1][2 * p],     a1, b[0], b[1]);
                    mma_f16(acc[1][2 * p + 1], a1, b[2], b[3]);
                }
            }
        }
        __syncthreads();
    }

    // ---- layer2 final store ----
    if (L == 1) {
#pragma unroll
        for (int mi = 0; mi < 2; mi++) {
            int r0g = row0 + wm + mi * 16 + g;
#pragma unroll
            for (int nj = 0; nj < 8; nj++) {
                int col = cb + nj * 8 + 2 * t;
                float ba = __ldg(&b2[col]), bb = __ldg(&b2[col + 1]);
                if (r0g < ND)
                    *(float2*)(out + (size_t)r0g * D + col) =
                        make_float2(acc[mi][nj][0] + ba, acc[mi][nj][1] + bb);
                if (r0g + 8 < ND)
                    *(float2*)(out + (size_t)(r0g + 8) * D + col) =
                        make_float2(acc[mi][nj][2] + ba, acc[mi][nj][3] + bb);
            }
        }
    }
}

// ---------------------------------------------------------------------------
extern "C" void kernel_launch(void* const* d_in, const int* in_sizes, int n_in,
                              void* d_out, int out_size) {
    const float* x_src = (const float*)d_in[0];
    const float* x_dst = (const float*)d_in[1];
    const void*  ei    = d_in[2];
    const void*  et    = d_in[3];
    const float* w1    = (const float*)d_in[4];
    const float* root1 = (const float*)d_in[5];
    const float* b1    = (const float*)d_in[6];
    const float* w2    = (const float*)d_in[7];
    const float* root2 = (const float*)d_in[8];
    const float* b2    = (const float*)d_in[9];
    float* out = (float*)d_out;
    int E = in_sizes[3];

    cudaFuncSetAttribute(fused_all, cudaFuncAttributeMaxDynamicSharedMemorySize, SMEM_T);

    prep_kernel<<<(ND * D / 4 + 255) / 256, 256>>>(w1, root1, w2, root2, x_src, x_dst);
    zero_kernel<<<2368, 256>>>();
    scatter_kernel<<<(E + 7) / 8, 256>>>(ei, et, E);

    fused_all<<<GRID_M, THREADS, SMEM_T>>>(b1, b2, out);
}

// round 13
// speedup vs baseline: 1.3547x; 1.0338x over previous
#include <cuda_runtime.h>
#include <cuda_fp16.h>
#include <cstdint>

constexpr int ND = 30000, D = 256, R = 8, KW = 2048;
constexpr int NCH    = 36;                    // K chunks of 64 (2304/64)
constexpr int MTILE  = 64;
constexpr int GRID_M = (ND + MTILE - 1) / MTILE;   // 469
constexpr int THREADS = 512;

// smem layout (bytes). Row strides 144 / 528 are ≡16 (mod 128): conflict-free ldmatrix.
constexpr int A_OFF    = 0;
constexpr int A_STAGE  = 64 * 144;            // 9216
constexpr int B_OFF    = 2 * A_STAGE;         // 18432
constexpr int B_STAGE  = 512 * 144;           // 73728
constexpr int H_OFF    = B_OFF + 2 * B_STAGE; // 165888
constexpr int H_STRIDE = 528;
constexpr int SMEM_T   = H_OFF + 64 * H_STRIDE;   // 199680

// device scratch (no allocations allowed)
__device__ __half g_sumh[(size_t)ND * KW];          // fp16 pre-scaled per-(dst,rel) means
__device__ float  g_cnt[ND * R];
__device__ __half g_xsh[(size_t)ND * D];            // x_src fp16
__device__ __half g_xdh[(size_t)ND * D];            // x_dst fp16
__device__ __half g_Bh[(size_t)2 * NCH * 256 * 64]; // [L][kc][n][k64] fp16
__device__ __half g_r2h[256 * 256];                 // root2 transposed [n][k]

// ---------------------------------------------------------------------------
__device__ __forceinline__ void mma_f16(float* c, const uint32_t* a,
                                        uint32_t b0, uint32_t b1) {
    asm volatile(
        "mma.sync.aligned.m16n8k16.row.col.f32.f16.f16.f32 "
        "{%0,%1,%2,%3}, {%4,%5,%6,%7}, {%8,%9}, {%0,%1,%2,%3};"
        : "+f"(c[0]), "+f"(c[1]), "+f"(c[2]), "+f"(c[3])
        : "r"(a[0]), "r"(a[1]), "r"(a[2]), "r"(a[3]), "r"(b0), "r"(b1));
}
__device__ __forceinline__ void ldsm_x4(uint32_t* r, uint32_t addr) {
    asm volatile("ldmatrix.sync.aligned.m8n8.x4.shared.b16 {%0,%1,%2,%3}, [%4];"
                 : "=r"(r[0]), "=r"(r[1]), "=r"(r[2]), "=r"(r[3]) : "r"(addr));
}
__device__ __forceinline__ void cp_async16(void* smem_dst, const void* gsrc) {
    uint32_t s = (uint32_t)__cvta_generic_to_shared(smem_dst);
    asm volatile("cp.async.cg.shared.global [%0], [%1], 16;" :: "r"(s), "l"(gsrc));
}
#define CP_COMMIT() asm volatile("cp.async.commit_group;" ::: "memory")
#define CP_WAIT0()  asm volatile("cp.async.wait_group 0;" ::: "memory")

// ---------------------------------------------------------------------------
// Kernel 0: prep — fp16 weights [L][kc64][n][k64]; root2 [n][k]; x_src/x_dst fp16
// ---------------------------------------------------------------------------
__global__ void prep_kernel(const float* __restrict__ w1, const float* __restrict__ r1,
                            const float* __restrict__ w2, const float* __restrict__ r2,
                            const float* __restrict__ xs, const float* __restrict__ xd) {
    int gid = blockIdx.x * blockDim.x + threadIdx.x;
    if (gid < 2 * NCH * 256 * 8) {
        int L   = gid / (NCH * 256 * 8);
        int rem = gid % (NCH * 256 * 8);
        int kc  = rem >> 11;
        int n   = (rem >> 3) & 255;
        int c8  = rem & 7;
        __half h8[8];
#pragma unroll
        for (int j = 0; j < 8; j++) {
            int k = kc * 64 + c8 * 8 + j;
            float x;
            if (L == 0) x = (k < KW) ? w1[(size_t)k * D + n] : r1[(size_t)(k - KW) * D + n];
            else        x = (k < KW) ? w2[(size_t)k * D + n] : 0.f;
            h8[j] = __float2half_rn(x);
        }
        *(uint4*)(g_Bh + ((size_t)(L * NCH + kc) * 256 + n) * 64 + c8 * 8) = *(uint4*)h8;
    }
    if (gid < 256 * 32) {
        int n = gid >> 5, c8 = gid & 31;
        __half h8[8];
#pragma unroll
        for (int j = 0; j < 8; j++)
            h8[j] = __float2half_rn(r2[(size_t)(c8 * 8 + j) * 256 + n]);
        *(uint4*)(g_r2h + (size_t)n * 256 + c8 * 8) = *(uint4*)h8;
    }
    if (gid < ND * D / 4) {
        float4 vs = __ldg((const float4*)xs + gid);
        float4 vd = __ldg((const float4*)xd + gid);
        ((__half2*)g_xsh)[gid * 2]     = __floats2half2_rn(vs.x, vs.y);
        ((__half2*)g_xsh)[gid * 2 + 1] = __floats2half2_rn(vs.z, vs.w);
        ((__half2*)g_xdh)[gid * 2]     = __floats2half2_rn(vd.x, vd.y);
        ((__half2*)g_xdh)[gid * 2 + 1] = __floats2half2_rn(vd.z, vd.w);
    }
}

// ---------------------------------------------------------------------------
// Kernel 1: zero fp16 sums + counts
// ---------------------------------------------------------------------------
__global__ void zero_kernel() {
    size_t stride = (size_t)gridDim.x * blockDim.x;
    size_t i = (size_t)blockIdx.x * blockDim.x + threadIdx.x;
    uint4 z = make_uint4(0, 0, 0, 0);
    size_t n16 = (size_t)ND * KW / 8;
    for (size_t j = i; j < n16; j += stride) ((uint4*)g_sumh)[j] = z;
    size_t nc4 = (size_t)ND * R / 4;
    for (size_t j = i; j < nc4; j += stride)
        ((float4*)g_cnt)[j] = make_float4(0.f, 0.f, 0.f, 0.f);
}

// ---------------------------------------------------------------------------
// Kernel 2a: count pass — one thread per edge
// ---------------------------------------------------------------------------
__global__ void count_kernel(const void* __restrict__ ei,
                             const void* __restrict__ et, int E) {
    int e = blockIdx.x * blockDim.x + threadIdx.x;
    if (e >= E) return;
    const int* ei32 = (const int*)ei;
    bool is64 = ((ei32[1] | ei32[3] | ei32[5] | ei32[7]) == 0);
    long long d, r;
    if (is64) {
        d = ((const long long*)ei)[E + e];
        r = ((const long long*)et)[e];
    } else {
        d = ei32[E + e];
        r = ((const int*)et)[e];
    }
    atomicAdd(&g_cnt[d * R + r], 1.0f);
}

// ---------------------------------------------------------------------------
// Kernel 2b: scatter-add PRE-SCALED fp16 (one warp per edge)
//   contribution = x_src[src] * (1/max(cnt,1)), f32 mul, fp16 round, fp16 red.
// ---------------------------------------------------------------------------
__global__ void scatter_kernel(const void* __restrict__ ei,
                               const void* __restrict__ et, int E) {
    int gw   = (blockIdx.x * blockDim.x + threadIdx.x) >> 5;
    int lane = threadIdx.x & 31;
    if (gw >= E) return;

    const int* ei32 = (const int*)ei;
    bool is64 = ((ei32[1] | ei32[3] | ei32[5] | ei32[7]) == 0);

    long long s, d, r;
    if (is64) {
        const long long* p = (const long long*)ei;
        s = p[gw]; d = p[E + gw]; r = ((const long long*)et)[gw];
    } else {
        s = ei32[gw]; d = ei32[E + gw]; r = ((const int*)et)[gw];
    }

    float c   = __ldg(&g_cnt[d * R + r]);
    float inv = 1.0f / fmaxf(c, 1.0f);

    uint4 v = __ldg((const uint4*)(g_xsh + (size_t)s * D) + lane);
    const __half* hv = (const __half*)&v;
    __half h8[8];
#pragma unroll
    for (int j = 0; j < 8; j++)
        h8[j] = __float2half_rn(__half2float(hv[j]) * inv);
    uint4 w = *(uint4*)h8;

    uint4* dst = (uint4*)(g_sumh + ((size_t)d * R + r) * D) + lane;
    asm volatile("red.global.add.noftz.v4.f16x2 [%0], {%1,%2,%3,%4};"
                 :: "l"(dst), "r"(w.x), "r"(w.y), "r"(w.z), "r"(w.w) : "memory");
}

// ---------------------------------------------------------------------------
// Kernel 3: fully-fused fp16 GEMM. A is pre-scaled fp16 -> pure cp.async path,
// no registers/STS in the loop. Round-10-proven S=2 structure otherwise.
// ---------------------------------------------------------------------------
__global__ __launch_bounds__(THREADS, 1)
void fused_all(const float* __restrict__ b1,
               const float* __restrict__ b2,
               float* __restrict__ out) {
    extern __shared__ char smx[];
    uint32_t smb = (uint32_t)__cvta_generic_to_shared(smx);

    int tid = threadIdx.x, wid = tid >> 5, lane = tid & 31;
    int g = lane >> 2, t = lane & 3;
    int L = wid >> 3, sub = wid & 7;
    int wm = (sub >> 2) * 32;       // 0 / 32
    int cb = (sub & 3) * 64;        // 0 / 64 / 128 / 192
    int row0 = blockIdx.x * MTILE;

    int lr = lane & 7, lh = (lane >> 3) & 1, lc = (lane >> 4) & 1;
    uint32_t a_loff  = (uint32_t)((wm + lr + lh * 8) * 144 + lc * 16);
    uint32_t b_loff  = (uint32_t)((L * 256 + cb + lr + lc * 8) * 144 + lh * 16);
    uint32_t br_loff = (uint32_t)((cb + lr + lc * 8) * 144 + lh * 16);
    uint32_t h_loff  = (uint32_t)((wm + lr + lh * 8) * H_STRIDE + lc * 16);

    float acc[2][8][4];
#pragma unroll
    for (int mi = 0; mi < 2; mi++)
#pragma unroll
        for (int nj = 0; nj < 8; nj++)
#pragma unroll
            for (int q = 0; q < 4; q++) acc[mi][nj][q] = 0.f;

    auto ldA = [&](int kc, int s) {
        int row = tid >> 3, c8 = tid & 7;       // 512 threads = 64 rows x 8
        int grow = row0 + row;
        if (grow >= ND) grow = 0;               // clamp: finite junk, never stored
        const __half* src = (kc < 32)
            ? g_sumh + (size_t)grow * KW + kc * 64 + c8 * 8
            : g_xdh + (size_t)grow * D + (kc - 32) * 64 + c8 * 8;
        cp_async16(smx + A_OFF + s * A_STAGE + row * 144 + c8 * 16, src);
    };
    auto ldB = [&](int kc, int s) {
#pragma unroll
        for (int i = 0; i < 8; i++) {
            int idx = tid + i * 512;            // 4096 x 16B
            int n5 = idx >> 3, c8 = idx & 7;
            int Lx = n5 >> 8, n = n5 & 255;
            cp_async16(smx + B_OFF + s * B_STAGE + n5 * 144 + c8 * 16,
                       g_Bh + ((size_t)(Lx * NCH + kc) * 256 + n) * 64 + c8 * 8);
        }
    };
    auto ldRootB = [&](int c, int s) {
#pragma unroll
        for (int i = 0; i < 4; i++) {
            int idx = tid + i * 512;            // 2048 x 16B
            int n = idx >> 3, c8 = idx & 7;
            cp_async16(smx + B_OFF + s * B_STAGE + n * 144 + c8 * 16,
                       g_r2h + (size_t)n * 256 + c * 64 + c8 * 8);
        }
    };
    auto compute = [&](int s) {
        uint32_t Ab = smb + A_OFF + s * A_STAGE + a_loff;
        uint32_t Bb = smb + B_OFF + s * B_STAGE + b_loff;
#pragma unroll
        for (int ks = 0; ks < 4; ks++) {
            uint32_t a0[4], a1[4];
            ldsm_x4(a0, Ab + ks * 32);
            ldsm_x4(a1, Ab + 16 * 144 + ks * 32);
#pragma unroll
            for (int p = 0; p < 4; p++) {
                uint32_t b[4];
                ldsm_x4(b, Bb + p * 16 * 144 + ks * 32);
                mma_f16(acc[0][2 * p],     a0, b[0], b[1]);
                mma_f16(acc[0][2 * p + 1], a0, b[2], b[3]);
                mma_f16(acc[1][2 * p],     a1, b[0], b[1]);
                mma_f16(acc[1][2 * p + 1], a1, b[2], b[3]);
            }
        }
    };

    // ---- main loop: 36 chunks of K=64; S=2; all loads cp.async ----
    ldB(0, 0); ldA(0, 0); CP_COMMIT();
    CP_WAIT0();
    __syncthreads();

    for (int k = 0; k < NCH; k++) {
        int s = k & 1;
        if (k + 1 < NCH) { ldB(k + 1, s ^ 1); ldA(k + 1, s ^ 1); CP_COMMIT(); }
        compute(s);
        CP_WAIT0();
        __syncthreads();
    }

    // ---- root2 prologue + layer1 epilogue (h -> smem fp16) ----
    ldRootB(0, 0); CP_COMMIT();
    if (L == 0) {
#pragma unroll
        for (int mi = 0; mi < 2; mi++) {
#pragma unroll
            for (int nj = 0; nj < 8; nj++) {
                int col = cb + nj * 8 + 2 * t;
                float ba = __ldg(&b1[col]), bb = __ldg(&b1[col + 1]);
                __half2 h0 = __floats2half2_rn(fmaxf(acc[mi][nj][0] + ba, 0.f),
                                               fmaxf(acc[mi][nj][1] + bb, 0.f));
                __half2 h1 = __floats2half2_rn(fmaxf(acc[mi][nj][2] + ba, 0.f),
                                               fmaxf(acc[mi][nj][3] + bb, 0.f));
                int r = wm + mi * 16 + g;
                *(__half2*)(smx + H_OFF + r * H_STRIDE + col * 2)       = h0;
                *(__half2*)(smx + H_OFF + (r + 8) * H_STRIDE + col * 2) = h1;
            }
        }
    }
    __syncthreads();

    // ---- root phase: layer2 acc += h @ root2 (4 chunks of K=64) ----
    for (int c = 0; c < 4; c++) {
        int s = c & 1;
        CP_WAIT0();
        __syncthreads();
        if (c + 1 < 4) { ldRootB(c + 1, s ^ 1); CP_COMMIT(); }
        if (L == 1) {
            uint32_t Hb = smb + H_OFF + h_loff + c * 128;
            uint32_t Bb = smb + B_OFF + s * B_STAGE + br_loff;
#pragma unroll
            for (int ks = 0; ks < 4; ks++) {
                uint32_t a0[4], a1[4];
                ldsm_x4(a0, Hb + ks * 32);
                ldsm_x4(a1, Hb + 16 * H_STRIDE + ks * 32);
#pragma unroll
                for (int p = 0; p < 4; p++) {
                    uint32_t b[4];
                    ldsm_x4(b, Bb + p * 16 * 144 + ks * 32);
                    mma_f16(acc[0][2 * p],     a0, b[0], b[1]);
                    mma_f16(acc[0][2 * p + 1], a0, b[2], b[3]);
                    mma_f16(acc[1][2 * p],     a1, b[0], b[1]);
                    mma_f16(acc[1][2 * p + 1], a1, b[2], b[3]);
                }
            }
        }
        __syncthreads();
    }

    // ---- layer2 final store ----
    if (L == 1) {
#pragma unroll
        for (int mi = 0; mi < 2; mi++) {
            int r0g = row0 + wm + mi * 16 + g;
#pragma unroll
            for (int nj = 0; nj < 8; nj++) {
                int col = cb + nj * 8 + 2 * t;
                float ba = __ldg(&b2[col]), bb = __ldg(&b2[col + 1]);
                if (r0g < ND)
                    *(float2*)(out + (size_t)r0g * D + col) =
                        make_float2(acc[mi][nj][0] + ba, acc[mi][nj][1] + bb);
                if (r0g + 8 < ND)
                    *(float2*)(out + (size_t)(r0g + 8) * D + col) =
                        make_float2(acc[mi][nj][2] + ba, acc[mi][nj][3] + bb);
            }
        }
    }
}

// ---------------------------------------------------------------------------
extern "C" void kernel_launch(void* const* d_in, const int* in_sizes, int n_in,
                              void* d_out, int out_size) {
    const float* x_src = (const float*)d_in[0];
    const float* x_dst = (const float*)d_in[1];
    const void*  ei    = d_in[2];
    const void*  et    = d_in[3];
    const float* w1    = (const float*)d_in[4];
    const float* root1 = (const float*)d_in[5];
    const float* b1    = (const float*)d_in[6];
    const float* w2    = (const float*)d_in[7];
    const float* root2 = (const float*)d_in[8];
    const float* b2    = (const float*)d_in[9];
    float* out = (float*)d_out;
    int E = in_sizes[3];

    cudaFuncSetAttribute(fused_all, cudaFuncAttributeMaxDynamicSharedMemorySize, SMEM_T);

    prep_kernel<<<(ND * D / 4 + 255) / 256, 256>>>(w1, root1, w2, root2, x_src, x_dst);
    zero_kernel<<<2368, 256>>>();
    count_kernel<<<(E + 255) / 256, 256>>>(ei, et, E);
    scatter_kernel<<<(E + 7) / 8, 256>>>(ei, et, E);

    fused_all<<<GRID_M, THREADS, SMEM_T>>>(b1, b2, out);
}

// round 14
// speedup vs baseline: 1.5456x; 1.1409x over previous
#include <cuda_runtime.h>
#include <cuda_fp16.h>
#include <cstdint>

constexpr int ND = 30000, D = 256, R = 8, KW = 2048;
constexpr int NCH    = 36;                    // K chunks of 64 (2304/64)
constexpr int MTILE  = 64;
constexpr int GRID_M = (ND + MTILE - 1) / MTILE;   // 469
constexpr int THREADS = 512;

// smem layout (bytes). 128B row stride + 16B-unit XOR swizzle (col ^ (row&7)).
constexpr int A_OFF    = 0;
constexpr int A_STAGE  = 64 * 128;            // 8192,  3 stages
constexpr int B_OFF    = 3 * A_STAGE;         // 24576
constexpr int B_STAGE  = 512 * 128;           // 65536, 3 stages
constexpr int H_OFF    = B_OFF + 2 * B_STAGE; // 155648 — H aliases B stage 2
constexpr int H_STRIDE = 528;                 // padded (unswizzled), ≡16 mod 128
constexpr int SMEM_T   = B_OFF + 3 * B_STAGE; // 221184

#define SWZ(col, row) ((((col) ^ ((row) & 7)) & 7) << 4)

// device scratch (no allocations allowed)
__device__ __half g_sumh[(size_t)ND * KW];          // fp16 pre-scaled per-(dst,rel) means
__device__ float  g_cnt[ND * R];
__device__ __half g_xsh[(size_t)ND * D];            // x_src fp16
__device__ __half g_xdh[(size_t)ND * D];            // x_dst fp16
__device__ __half g_Bh[(size_t)2 * NCH * 256 * 64]; // [L][kc][n][k64] fp16
__device__ __half g_r2h[256 * 256];                 // root2 transposed [n][k]

// ---------------------------------------------------------------------------
__device__ __forceinline__ void mma_f16(float* c, const uint32_t* a,
                                        uint32_t b0, uint32_t b1) {
    asm volatile(
        "mma.sync.aligned.m16n8k16.row.col.f32.f16.f16.f32 "
        "{%0,%1,%2,%3}, {%4,%5,%6,%7}, {%8,%9}, {%0,%1,%2,%3};"
        : "+f"(c[0]), "+f"(c[1]), "+f"(c[2]), "+f"(c[3])
        : "r"(a[0]), "r"(a[1]), "r"(a[2]), "r"(a[3]), "r"(b0), "r"(b1));
}
__device__ __forceinline__ void ldsm_x4(uint32_t* r, uint32_t addr) {
    asm volatile("ldmatrix.sync.aligned.m8n8.x4.shared.b16 {%0,%1,%2,%3}, [%4];"
                 : "=r"(r[0]), "=r"(r[1]), "=r"(r[2]), "=r"(r[3]) : "r"(addr));
}
__device__ __forceinline__ void cp_async16(void* smem_dst, const void* gsrc) {
    uint32_t s = (uint32_t)__cvta_generic_to_shared(smem_dst);
    asm volatile("cp.async.cg.shared.global [%0], [%1], 16;" :: "r"(s), "l"(gsrc));
}
#define CP_COMMIT() asm volatile("cp.async.commit_group;" ::: "memory")
#define CP_WAIT(n)  asm volatile("cp.async.wait_group %0;" :: "n"(n) : "memory")

// ---------------------------------------------------------------------------
// Kernel 0: prep — fp16 weights [L][kc64][n][k64]; root2 [n][k]; x_src/x_dst fp16
// ---------------------------------------------------------------------------
__global__ void prep_kernel(const float* __restrict__ w1, const float* __restrict__ r1,
                            const float* __restrict__ w2, const float* __restrict__ r2,
                            const float* __restrict__ xs, const float* __restrict__ xd) {
    int gid = blockIdx.x * blockDim.x + threadIdx.x;
    if (gid < 2 * NCH * 256 * 8) {
        int L   = gid / (NCH * 256 * 8);
        int rem = gid % (NCH * 256 * 8);
        int kc  = rem >> 11;
        int n   = (rem >> 3) & 255;
        int c8  = rem & 7;
        __half h8[8];
#pragma unroll
        for (int j = 0; j < 8; j++) {
            int k = kc * 64 + c8 * 8 + j;
            float x;
            if (L == 0) x = (k < KW) ? w1[(size_t)k * D + n] : r1[(size_t)(k - KW) * D + n];
            else        x = (k < KW) ? w2[(size_t)k * D + n] : 0.f;
            h8[j] = __float2half_rn(x);
        }
        *(uint4*)(g_Bh + ((size_t)(L * NCH + kc) * 256 + n) * 64 + c8 * 8) = *(uint4*)h8;
    }
    if (gid < 256 * 32) {
        int n = gid >> 5, c8 = gid & 31;
        __half h8[8];
#pragma unroll
        for (int j = 0; j < 8; j++)
            h8[j] = __float2half_rn(r2[(size_t)(c8 * 8 + j) * 256 + n]);
        *(uint4*)(g_r2h + (size_t)n * 256 + c8 * 8) = *(uint4*)h8;
    }
    if (gid < ND * D / 4) {
        float4 vs = __ldg((const float4*)xs + gid);
        float4 vd = __ldg((const float4*)xd + gid);
        ((__half2*)g_xsh)[gid * 2]     = __floats2half2_rn(vs.x, vs.y);
        ((__half2*)g_xsh)[gid * 2 + 1] = __floats2half2_rn(vs.z, vs.w);
        ((__half2*)g_xdh)[gid * 2]     = __floats2half2_rn(vd.x, vd.y);
        ((__half2*)g_xdh)[gid * 2 + 1] = __floats2half2_rn(vd.z, vd.w);
    }
}

// ---------------------------------------------------------------------------
// Kernel 1: zero fp16 sums + counts
// ---------------------------------------------------------------------------
__global__ void zero_kernel() {
    size_t stride = (size_t)gridDim.x * blockDim.x;
    size_t i = (size_t)blockIdx.x * blockDim.x + threadIdx.x;
    uint4 z = make_uint4(0, 0, 0, 0);
    size_t n16 = (size_t)ND * KW / 8;
    for (size_t j = i; j < n16; j += stride) ((uint4*)g_sumh)[j] = z;
    size_t nc4 = (size_t)ND * R / 4;
    for (size_t j = i; j < nc4; j += stride)
        ((float4*)g_cnt)[j] = make_float4(0.f, 0.f, 0.f, 0.f);
}

// ---------------------------------------------------------------------------
// Kernel 2a: count pass — one thread per edge
// ---------------------------------------------------------------------------
__global__ void count_kernel(const void* __restrict__ ei,
                             const void* __restrict__ et, int E) {
    int e = blockIdx.x * blockDim.x + threadIdx.x;
    if (e >= E) return;
    const int* ei32 = (const int*)ei;
    bool is64 = ((ei32[1] | ei32[3] | ei32[5] | ei32[7]) == 0);
    long long d, r;
    if (is64) {
        d = ((const long long*)ei)[E + e];
        r = ((const long long*)et)[e];
    } else {
        d = ei32[E + e];
        r = ((const int*)et)[e];
    }
    atomicAdd(&g_cnt[d * R + r], 1.0f);
}

// ---------------------------------------------------------------------------
// Kernel 2b: scatter-add PRE-SCALED fp16 (one warp per edge)
// ---------------------------------------------------------------------------
__global__ void scatter_kernel(const void* __restrict__ ei,
                               const void* __restrict__ et, int E) {
    int gw   = (blockIdx.x * blockDim.x + threadIdx.x) >> 5;
    int lane = threadIdx.x & 31;
    if (gw >= E) return;

    const int* ei32 = (const int*)ei;
    bool is64 = ((ei32[1] | ei32[3] | ei32[5] | ei32[7]) == 0);

    long long s, d, r;
    if (is64) {
        const long long* p = (const long long*)ei;
        s = p[gw]; d = p[E + gw]; r = ((const long long*)et)[gw];
    } else {
        s = ei32[gw]; d = ei32[E + gw]; r = ((const int*)et)[gw];
    }

    float c   = __ldg(&g_cnt[d * R + r]);
    float inv = 1.0f / fmaxf(c, 1.0f);

    uint4 v = __ldg((const uint4*)(g_xsh + (size_t)s * D) + lane);
    const __half* hv = (const __half*)&v;
    __half h8[8];
#pragma unroll
    for (int j = 0; j < 8; j++)
        h8[j] = __float2half_rn(__half2float(hv[j]) * inv);
    uint4 w = *(uint4*)h8;

    uint4* dst = (uint4*)(g_sumh + ((size_t)d * R + r) * D) + lane;
    asm volatile("red.global.add.noftz.v4.f16x2 [%0], {%1,%2,%3,%4};"
                 :: "l"(dst), "r"(w.x), "r"(w.y), "r"(w.z), "r"(w.w) : "memory");
}

// ---------------------------------------------------------------------------
// Kernel 3: fully-fused fp16 GEMM. Swizzled 128B-stride tiles, 3-stage
// pipeline with lookahead 2 + wait_group(1).
// ---------------------------------------------------------------------------
__global__ __launch_bounds__(THREADS, 1)
void fused_all(const float* __restrict__ b1,
               const float* __restrict__ b2,
               float* __restrict__ out) {
    extern __shared__ char smx[];
    uint32_t smb = (uint32_t)__cvta_generic_to_shared(smx);

    int tid = threadIdx.x, wid = tid >> 5, lane = tid & 31;
    int g = lane >> 2, t = lane & 3;
    int L = wid >> 3, sub = wid & 7;
    int wm = (sub >> 2) * 32;       // 0 / 32
    int cb = (sub & 3) * 64;        // 0 / 64 / 128 / 192
    int row0 = blockIdx.x * MTILE;

    // ldmatrix lane mapping
    int lr = lane & 7, lh = (lane >> 3) & 1, lc = (lane >> 4) & 1;
    int rowA  = wm + lr + lh * 8;              // + 16 for a1 (same &7)
    int rowB  = L * 256 + cb + lr + lc * 8;    // + p*16 (same &7)
    int rowBr = cb + lr + lc * 8;
    uint32_t h_loff = (uint32_t)((wm + lr + lh * 8) * H_STRIDE + lc * 16);

    float acc[2][8][4];
#pragma unroll
    for (int mi = 0; mi < 2; mi++)
#pragma unroll
        for (int nj = 0; nj < 8; nj++)
#pragma unroll
            for (int q = 0; q < 4; q++) acc[mi][nj][q] = 0.f;

    auto ldA = [&](int kc, int s) {
        int row = tid >> 3, c8 = tid & 7;       // 512 threads = 64 rows x 8
        int grow = row0 + row;
        if (grow >= ND) grow = 0;               // clamp: finite junk, never stored
        const __half* src = (kc < 32)
            ? g_sumh + (size_t)grow * KW + kc * 64 + c8 * 8
            : g_xdh + (size_t)grow * D + (kc - 32) * 64 + c8 * 8;
        cp_async16(smx + A_OFF + s * A_STAGE + row * 128 + SWZ(c8, row), src);
    };
    auto ldB = [&](int kc, int s) {
#pragma unroll
        for (int i = 0; i < 8; i++) {
            int idx = tid + i * 512;            // 4096 x 16B
            int n5 = idx >> 3, c8 = idx & 7;
            int Lx = n5 >> 8, n = n5 & 255;
            cp_async16(smx + B_OFF + s * B_STAGE + n5 * 128 + SWZ(c8, n5),
                       g_Bh + ((size_t)(Lx * NCH + kc) * 256 + n) * 64 + c8 * 8);
        }
    };
    auto ldRootB = [&](int c, int s) {
#pragma unroll
        for (int i = 0; i < 4; i++) {
            int idx = tid + i * 512;            // 2048 x 16B (256 rows x 8)
            int n = idx >> 3, c8 = idx & 7;
            cp_async16(smx + B_OFF + s * B_STAGE + n * 128 + SWZ(c8, n),
                       g_r2h + (size_t)n * 256 + c * 64 + c8 * 8);
        }
    };
    auto compute = [&](int s) {
        uint32_t Ab = smb + A_OFF + s * A_STAGE + rowA * 128;
        uint32_t Bb = smb + B_OFF + s * B_STAGE + rowB * 128;
#pragma unroll
        for (int ks = 0; ks < 4; ks++) {
            uint32_t a0[4], a1[4];
            int colA = lc + 2 * ks;
            ldsm_x4(a0, Ab + SWZ(colA, rowA));
            ldsm_x4(a1, Ab + 16 * 128 + SWZ(colA, rowA));
            int colB = lh + 2 * ks;
            uint32_t bsw = SWZ(colB, rowB);
#pragma unroll
            for (int p = 0; p < 4; p++) {
                uint32_t b[4];
                ldsm_x4(b, Bb + p * 16 * 128 + bsw);
                mma_f16(acc[0][2 * p],     a0, b[0], b[1]);
                mma_f16(acc[0][2 * p + 1], a0, b[2], b[3]);
                mma_f16(acc[1][2 * p],     a1, b[0], b[1]);
                mma_f16(acc[1][2 * p + 1], a1, b[2], b[3]);
            }
        }
    };

    // ---- main loop: 36 chunks; S=3, lookahead 2, wait_group(1) ----
    // Race proof: loads issued at iter k target stage (k+2)%3, whose previous
    // reader compute(k-1) finished before the iter-(k-1) barrier preceding
    // this issue. wait(1) guarantees chunk k+1's group before iter k+1 reads.
    ldB(0, 0); ldA(0, 0); CP_COMMIT();
    ldB(1, 1); ldA(1, 1); CP_COMMIT();
    CP_WAIT(1);
    __syncthreads();

    for (int k = 0; k < NCH; k++) {
        if (k + 2 < NCH) { ldB(k + 2, (k + 2) % 3); ldA(k + 2, (k + 2) % 3); }
        CP_COMMIT();                 // empty groups pad the tail
        compute(k % 3);
        CP_WAIT(1);
        __syncthreads();
    }

    // ---- root2 prologue + layer1 epilogue (h -> smem fp16, aliases B stage 2) ----
    ldRootB(0, 0); CP_COMMIT();
    if (L == 0) {
#pragma unroll
        for (int mi = 0; mi < 2; mi++) {
#pragma unroll
            for (int nj = 0; nj < 8; nj++) {
                int col = cb + nj * 8 + 2 * t;
                float ba = __ldg(&b1[col]), bb = __ldg(&b1[col + 1]);
                __half2 h0 = __floats2half2_rn(fmaxf(acc[mi][nj][0] + ba, 0.f),
                                               fmaxf(acc[mi][nj][1] + bb, 0.f));
                __half2 h1 = __floats2half2_rn(fmaxf(acc[mi][nj][2] + ba, 0.f),
                                               fmaxf(acc[mi][nj][3] + bb, 0.f));
                int r = wm + mi * 16 + g;
                *(__half2*)(smx + H_OFF + r * H_STRIDE + col * 2)       = h0;
                *(__half2*)(smx + H_OFF + (r + 8) * H_STRIDE + col * 2) = h1;
            }
        }
    }
    __syncthreads();

    // ---- root phase: layer2 acc += h @ root2 (4 chunks of K=64, B stages 0/1) ----
    for (int c = 0; c < 4; c++) {
        int s = c & 1;
        CP_WAIT(0);
        __syncthreads();
        if (c + 1 < 4) { ldRootB(c + 1, s ^ 1); CP_COMMIT(); }
        if (L == 1) {
            uint32_t Hb = smb + H_OFF + h_loff + c * 128;
            uint32_t Bb = smb + B_OFF + s * B_STAGE + rowBr * 128;
#pragma unroll
            for (int ks = 0; ks < 4; ks++) {
                uint32_t a0[4], a1[4];
                ldsm_x4(a0, Hb + ks * 32);
                ldsm_x4(a1, Hb + 16 * H_STRIDE + ks * 32);
                int colB = lh + 2 * ks;
                uint32_t bsw = SWZ(colB, rowBr);
#pragma unroll
                for (int p = 0; p < 4; p++) {
                    uint32_t b[4];
                    ldsm_x4(b, Bb + p * 16 * 128 + bsw);
                    mma_f16(acc[0][2 * p],     a0, b[0], b[1]);
                    mma_f16(acc[0][2 * p + 1], a0, b[2], b[3]);
                    mma_f16(acc[1][2 * p],     a1, b[0], b[1]);
                    mma_f16(acc[1][2 * p + 1], a1, b[2], b[3]);
                }
            }
        }
        __syncthreads();
    }

    // ---- layer2 final store ----
    if (L == 1) {
#pragma unroll
        for (int mi = 0; mi < 2; mi++) {
            int r0g = row0 + wm + mi * 16 + g;
#pragma unroll
            for (int nj = 0; nj < 8; nj++) {
                int col = cb + nj * 8 + 2 * t;
                float ba = __ldg(&b2[col]), bb = __ldg(&b2[col + 1]);
                if (r0g < ND)
                    *(float2*)(out + (size_t)r0g * D + col) =
                        make_float2(acc[0 + 0][nj][0] * 0.f + acc[mi][nj][0] + ba,
                                    acc[mi][nj][1] + bb);
                if (r0g + 8 < ND)
                    *(float2*)(out + (size_t)(r0g + 8) * D + col) =
                        make_float2(acc[mi][nj][2] + ba, acc[mi][nj][3] + bb);
            }
        }
    }
}

// ---------------------------------------------------------------------------
extern "C" void kernel_launch(void* const* d_in, const int* in_sizes, int n_in,
                              void* d_out, int out_size) {
    const float* x_src = (const float*)d_in[0];
    const float* x_dst = (const float*)d_in[1];
    const void*  ei    = d_in[2];
    const void*  et    = d_in[3];
    const float* w1    = (const float*)d_in[4];
    const float* root1 = (const float*)d_in[5];
    const float* b1    = (const float*)d_in[6];
    const float* w2    = (const float*)d_in[7];
    const float* root2 = (const float*)d_in[8];
    const float* b2    = (const float*)d_in[9];
    float* out = (float*)d_out;
    int E = in_sizes[3];

    cudaFuncSetAttribute(fused_all, cudaFuncAttributeMaxDynamicSharedMemorySize, SMEM_T);

    prep_kernel<<<(ND * D / 4 + 255) / 256, 256>>>(w1, root1, w2, root2, x_src, x_dst);
    zero_kernel<<<2368, 256>>>();
    count_kernel<<<(E + 255) / 256, 256>>>(ei, et, E);
    scatter_kernel<<<(E + 7) / 8, 256>>>(ei, et, E);

    fused_all<<<GRID_M, THREADS, SMEM_T>>>(b1, b2, out);
}